// round 4
// baseline (speedup 1.0000x reference)
#include <cuda_runtime.h>
#include <math.h>

#define BATCH 8
#define DET   512
#define NANG  180
#define PADW  768
#define POFF  128
#define NROWS (BATCH * NANG)

// G2[k] = g[|k-512|] : shifted ramp-filter spatial kernel (monotone indexing).
__device__ float g_filt2[1024];
// Filtered projections, [b][a][d], zero-padded: (b*NANG+a)*PADW + POFF + d.
__device__ float g_scratch[NROWS * PADW];
// Lerp-ready pairs: g_pairs[row][d] = (y[d], y[d+1]-y[d]).
__device__ float2 g_pairs[NROWS * PADW];

__global__ void init_g_kernel() {
    int k = blockIdx.x * blockDim.x + threadIdx.x;
    if (k >= 1024) return;
    int m = k - 512; if (m < 0) m = -m;
    float v = 0.0f;
    if (m == 0) v = 0.5f;
    else if (m & 1) {
        double pm = 3.141592653589793 * (double)m;
        v = (float)(-2.0 / (pm * pm));
    }
    g_filt2[k] = v;
}

__global__ void zero_scratch_kernel() {
    int i = blockIdx.x * blockDim.x + threadIdx.x;
    if (i < NROWS * PADW) g_scratch[i] = 0.0f;
}

// Ramp filter as symmetric Toeplitz matvec, parity split (even-|m| taps zero).
__global__ void __launch_bounds__(192) filt_kernel(const float* __restrict__ x) {
    __shared__ float gs[1024];
    for (int i = threadIdx.x; i < 1024; i += 192) gs[i] = g_filt2[i];
    __syncthreads();

    int b = blockIdx.y;
    int dbase = blockIdx.x * 8;        // always even
    int a = threadIdx.x;
    if (a >= NANG) return;

    const float* xb = x + (size_t)b * DET * NANG + a;

    float acc0 = 0.5f * xb[(dbase + 0) * NANG];
    float acc1 = 0.5f * xb[(dbase + 1) * NANG];
    float acc2 = 0.5f * xb[(dbase + 2) * NANG];
    float acc3 = 0.5f * xb[(dbase + 3) * NANG];
    float acc4 = 0.5f * xb[(dbase + 4) * NANG];
    float acc5 = 0.5f * xb[(dbase + 5) * NANG];
    float acc6 = 0.5f * xb[(dbase + 6) * NANG];
    float acc7 = 0.5f * xb[(dbase + 7) * NANG];

    const float* gp = gs + 512 + dbase;
    const float* xr = xb;

    #pragma unroll 4
    for (int j = 0; j < DET; j += 2) {
        float xe = xr[0];
        float xo = xr[NANG];
        xr += 2 * NANG;
        const float* g0 = gp - j;
        float gm1 = g0[-1], g1 = g0[1], g3 = g0[3], g5 = g0[5], g7 = g0[7];
        acc1 = fmaf(g1, xe, acc1);
        acc3 = fmaf(g3, xe, acc3);
        acc5 = fmaf(g5, xe, acc5);
        acc7 = fmaf(g7, xe, acc7);
        acc0 = fmaf(gm1, xo, acc0);
        acc2 = fmaf(g1,  xo, acc2);
        acc4 = fmaf(g3,  xo, acc4);
        acc6 = fmaf(g5,  xo, acc6);
    }

    float* out = g_scratch + ((size_t)b * NANG + a) * PADW + POFF + dbase;
    out[0] = acc0; out[1] = acc1; out[2] = acc2; out[3] = acc3;
    out[4] = acc4; out[5] = acc5; out[6] = acc6; out[7] = acc7;
}

// Convert to lerp-ready (v0, v1-v0) pairs.
// NOTE: PADW=768 is NOT a power of two -> must use true modulo, not & (PADW-1).
__global__ void __launch_bounds__(256) pack_kernel() {
    int idx = blockIdx.x * blockDim.x + threadIdx.x;
    if (idx >= NROWS * PADW) return;
    int row = idx / PADW;
    int d   = idx - row * PADW;
    float v0 = g_scratch[idx];
    float v1 = (d + 1 < PADW && idx + 1 < NROWS * PADW) ? g_scratch[idx + 1] : 0.0f;
    g_pairs[idx] = make_float2(v0, v1 - v0);
}

// Backprojection: 4 pixels per thread (iy0 + {0,8,16,24}), pair loads, no predicates.
__global__ void __launch_bounds__(256) bp_kernel(float* __restrict__ out) {
    __shared__ float2 cs[NANG];
    int tid = threadIdx.y * 32 + threadIdx.x;
    if (tid < NANG) {
        float th = (float)tid * 0.017453292519943295f;
        float s, c;
        sincosf(th, &s, &c);
        cs[tid] = make_float2(c * 255.5f, s * 255.5f);
    }
    __syncthreads();

    int b   = blockIdx.z;
    int ix  = blockIdx.x * 32 + threadIdx.x;
    int iy0 = blockIdx.y * 32 + threadIdx.y;   // pixels iy0, +8, +16, +24

    const float step = 2.0f / 511.0f;
    // no-FMA grid coords to track jnp.linspace rounding (mask sensitivity)
    float ux  = __fadd_rn(__fmul_rn((float)ix,        step), -1.0f);
    float uy0 = __fadd_rn(__fmul_rn((float)(iy0),      step), -1.0f);
    float uy1 = __fadd_rn(__fmul_rn((float)(iy0 + 8),  step), -1.0f);
    float uy2 = __fadd_rn(__fmul_rn((float)(iy0 + 16), step), -1.0f);
    float uy3 = __fadd_rn(__fmul_rn((float)(iy0 + 24), step), -1.0f);

    const float2* p = g_pairs + (size_t)b * NANG * PADW + POFF;

    float acc0 = 0.0f, acc1 = 0.0f, acc2 = 0.0f, acc3 = 0.0f;
    #pragma unroll 4
    for (int a = 0; a < NANG; a++, p += PADW) {
        float2 t = cs[a];
        float xbase = fmaf(ux, t.x, 255.5f);
        float yi0 = fmaf(-uy0, t.y, xbase);
        float yi1 = fmaf(-uy1, t.y, xbase);
        float yi2 = fmaf(-uy2, t.y, xbase);
        float yi3 = fmaf(-uy3, t.y, xbase);

        float f0 = floorf(yi0), f1 = floorf(yi1), f2 = floorf(yi2), f3 = floorf(yi3);
        int   i0 = (int)f0,     i1 = (int)f1,     i2 = (int)f2,     i3 = (int)f3;
        float w0 = yi0 - f0,    w1 = yi1 - f1,    w2 = yi2 - f2,    w3 = yi3 - f3;

        float2 p0 = p[i0];
        float2 p1 = p[i1];
        float2 p2 = p[i2];
        float2 p3 = p[i3];
        acc0 += fmaf(w0, p0.y, p0.x);
        acc1 += fmaf(w1, p1.y, p1.x);
        acc2 += fmaf(w2, p2.y, p2.x);
        acc3 += fmaf(w3, p3.y, p3.x);
    }

    const float scale = 0.008726646259971648f;  // pi/360
    float uxx = __fmul_rn(ux, ux);
    float r20 = __fadd_rn(uxx, __fmul_rn(uy0, uy0));
    float r21 = __fadd_rn(uxx, __fmul_rn(uy1, uy1));
    float r22 = __fadd_rn(uxx, __fmul_rn(uy2, uy2));
    float r23 = __fadd_rn(uxx, __fmul_rn(uy3, uy3));

    float* o = out + ((size_t)b * 512 + iy0) * 512 + ix;
    o[0]          = (r20 <= 1.0f) ? acc0 * scale : 0.0f;
    o[8 * 512]    = (r21 <= 1.0f) ? acc1 * scale : 0.0f;
    o[16 * 512]   = (r22 <= 1.0f) ? acc2 * scale : 0.0f;
    o[24 * 512]   = (r23 <= 1.0f) ? acc3 * scale : 0.0f;
}

extern "C" void kernel_launch(void* const* d_in, const int* in_sizes, int n_in,
                              void* d_out, int out_size) {
    const float* x = (const float*)d_in[0];
    float* out = (float*)d_out;

    init_g_kernel<<<2, 512>>>();
    zero_scratch_kernel<<<(NROWS * PADW + 255) / 256, 256>>>();
    filt_kernel<<<dim3(DET / 8, BATCH), 192>>>(x);
    pack_kernel<<<(NROWS * PADW + 255) / 256, 256>>>();
    bp_kernel<<<dim3(512 / 32, 512 / 32, BATCH), dim3(32, 8)>>>(out);
}

// round 6
// speedup vs baseline: 1.0265x; 1.0265x over previous
#include <cuda_runtime.h>
#include <cuda_fp16.h>
#include <math.h>

#define BATCH 8
#define DET   512
#define NANG  180
#define PADW  768
#define POFF  128
#define NROWS (BATCH * NANG)

// G2[k] = g[|k-512|] : shifted ramp-filter spatial kernel (monotone indexing).
__device__ float g_filt2[1024];
// Filtered projections, [b][a][d], zero-padded: (b*NANG+a)*PADW + POFF + d.
__device__ float g_scratch[NROWS * PADW];
// Lerp-ready half2 taps: g_pairsh[row][d] = ( y[d], y[d+1]-y[d] )  -> 4 B/tap.
__device__ __half2 g_pairsh[NROWS * PADW];

__global__ void init_g_kernel() {
    int k = blockIdx.x * blockDim.x + threadIdx.x;
    if (k >= 1024) return;
    int m = k - 512; if (m < 0) m = -m;
    float v = 0.0f;
    if (m == 0) v = 0.5f;
    else if (m & 1) {
        double pm = 3.141592653589793 * (double)m;
        v = (float)(-2.0 / (pm * pm));
    }
    g_filt2[k] = v;
}

__global__ void zero_scratch_kernel() {
    int i = blockIdx.x * blockDim.x + threadIdx.x;
    if (i < NROWS * PADW) g_scratch[i] = 0.0f;
}

// Ramp filter as symmetric Toeplitz matvec, parity split (even-|m| taps zero).
__global__ void __launch_bounds__(192) filt_kernel(const float* __restrict__ x) {
    __shared__ float gs[1024];
    for (int i = threadIdx.x; i < 1024; i += 192) gs[i] = g_filt2[i];
    __syncthreads();

    int b = blockIdx.y;
    int dbase = blockIdx.x * 8;        // always even
    int a = threadIdx.x;
    if (a >= NANG) return;

    const float* xb = x + (size_t)b * DET * NANG + a;

    float acc0 = 0.5f * xb[(dbase + 0) * NANG];
    float acc1 = 0.5f * xb[(dbase + 1) * NANG];
    float acc2 = 0.5f * xb[(dbase + 2) * NANG];
    float acc3 = 0.5f * xb[(dbase + 3) * NANG];
    float acc4 = 0.5f * xb[(dbase + 4) * NANG];
    float acc5 = 0.5f * xb[(dbase + 5) * NANG];
    float acc6 = 0.5f * xb[(dbase + 6) * NANG];
    float acc7 = 0.5f * xb[(dbase + 7) * NANG];

    const float* gp = gs + 512 + dbase;
    const float* xr = xb;

    #pragma unroll 4
    for (int j = 0; j < DET; j += 2) {
        float xe = xr[0];
        float xo = xr[NANG];
        xr += 2 * NANG;
        const float* g0 = gp - j;
        float gm1 = g0[-1], g1 = g0[1], g3 = g0[3], g5 = g0[5], g7 = g0[7];
        acc1 = fmaf(g1, xe, acc1);
        acc3 = fmaf(g3, xe, acc3);
        acc5 = fmaf(g5, xe, acc5);
        acc7 = fmaf(g7, xe, acc7);
        acc0 = fmaf(gm1, xo, acc0);
        acc2 = fmaf(g1,  xo, acc2);
        acc4 = fmaf(g3,  xo, acc4);
        acc6 = fmaf(g5,  xo, acc6);
    }

    float* out = g_scratch + ((size_t)b * NANG + a) * PADW + POFF + dbase;
    out[0] = acc0; out[1] = acc1; out[2] = acc2; out[3] = acc3;
    out[4] = acc4; out[5] = acc5; out[6] = acc6; out[7] = acc7;
}

// Convert to lerp-ready half2 (v0, v1-v0) taps.
// NOTE: PADW=768 is NOT a power of two -> true modulo, not & (PADW-1).
__global__ void __launch_bounds__(256) pack_kernel() {
    int idx = blockIdx.x * blockDim.x + threadIdx.x;
    if (idx >= NROWS * PADW) return;
    int row = idx / PADW;
    int d   = idx - row * PADW;
    float v0 = g_scratch[idx];
    float v1 = (d + 1 < PADW && idx + 1 < NROWS * PADW) ? g_scratch[idx + 1] : 0.0f;
    g_pairsh[idx] = __floats2half2_rn(v0, v1 - v0);
}

// Backprojection: 4 pixels/thread (iy0 + {0,8,16,24}), one LDG.32 per tap.
__global__ void __launch_bounds__(256) bp_kernel(float* __restrict__ out) {
    __shared__ float2 cs[NANG];
    int tid = threadIdx.y * 32 + threadIdx.x;
    if (tid < NANG) {
        float th = (float)tid * 0.017453292519943295f;
        float s, c;
        sincosf(th, &s, &c);
        cs[tid] = make_float2(c * 255.5f, s * 255.5f);
    }
    __syncthreads();

    int b   = blockIdx.z;
    int ix  = blockIdx.x * 32 + threadIdx.x;
    int iy0 = blockIdx.y * 32 + threadIdx.y;   // pixels iy0, +8, +16, +24

    const float step = 2.0f / 511.0f;
    // no-FMA grid coords to track jnp.linspace rounding (mask sensitivity)
    float ux  = __fadd_rn(__fmul_rn((float)ix,        step), -1.0f);
    float uy0 = __fadd_rn(__fmul_rn((float)(iy0),      step), -1.0f);
    float uy1 = __fadd_rn(__fmul_rn((float)(iy0 + 8),  step), -1.0f);
    float uy2 = __fadd_rn(__fmul_rn((float)(iy0 + 16), step), -1.0f);
    float uy3 = __fadd_rn(__fmul_rn((float)(iy0 + 24), step), -1.0f);

    const __half2* p = g_pairsh + (size_t)b * NANG * PADW + POFF;

    float acc0 = 0.0f, acc1 = 0.0f, acc2 = 0.0f, acc3 = 0.0f;
    #pragma unroll 4
    for (int a = 0; a < NANG; a++, p += PADW) {
        float2 t = cs[a];
        float xbase = fmaf(ux, t.x, 255.5f);
        float yi0 = fmaf(-uy0, t.y, xbase);
        float yi1 = fmaf(-uy1, t.y, xbase);
        float yi2 = fmaf(-uy2, t.y, xbase);
        float yi3 = fmaf(-uy3, t.y, xbase);

        float f0 = floorf(yi0), f1 = floorf(yi1), f2 = floorf(yi2), f3 = floorf(yi3);
        int   i0 = (int)f0,     i1 = (int)f1,     i2 = (int)f2,     i3 = (int)f3;
        float w0 = yi0 - f0,    w1 = yi1 - f1,    w2 = yi2 - f2,    w3 = yi3 - f3;

        float2 q0 = __half22float2(p[i0]);
        float2 q1 = __half22float2(p[i1]);
        float2 q2 = __half22float2(p[i2]);
        float2 q3 = __half22float2(p[i3]);
        acc0 += fmaf(w0, q0.y, q0.x);
        acc1 += fmaf(w1, q1.y, q1.x);
        acc2 += fmaf(w2, q2.y, q2.x);
        acc3 += fmaf(w3, q3.y, q3.x);
    }

    const float scale = 0.008726646259971648f;  // pi/360
    float uxx = __fmul_rn(ux, ux);
    float r20 = __fadd_rn(uxx, __fmul_rn(uy0, uy0));
    float r21 = __fadd_rn(uxx, __fmul_rn(uy1, uy1));
    float r22 = __fadd_rn(uxx, __fmul_rn(uy2, uy2));
    float r23 = __fadd_rn(uxx, __fmul_rn(uy3, uy3));

    float* o = out + ((size_t)b * 512 + iy0) * 512 + ix;
    o[0]          = (r20 <= 1.0f) ? acc0 * scale : 0.0f;
    o[8 * 512]    = (r21 <= 1.0f) ? acc1 * scale : 0.0f;
    o[16 * 512]   = (r22 <= 1.0f) ? acc2 * scale : 0.0f;
    o[24 * 512]   = (r23 <= 1.0f) ? acc3 * scale : 0.0f;
}

extern "C" void kernel_launch(void* const* d_in, const int* in_sizes, int n_in,
                              void* d_out, int out_size) {
    const float* x = (const float*)d_in[0];
    float* out = (float*)d_out;

    init_g_kernel<<<2, 512>>>();
    zero_scratch_kernel<<<(NROWS * PADW + 255) / 256, 256>>>();
    filt_kernel<<<dim3(DET / 8, BATCH), 192>>>(x);
    pack_kernel<<<(NROWS * PADW + 255) / 256, 256>>>();
    bp_kernel<<<dim3(512 / 32, 512 / 32, BATCH), dim3(32, 8)>>>(out);
}

// round 10
// speedup vs baseline: 1.2501x; 1.2178x over previous
#include <cuda_runtime.h>
#include <math.h>

#define BATCH 8
#define DET   512
#define NANG  180
#define PADW  768
#define POFF  128
#define NROWS (BATCH * NANG)

__device__ float g_filt2[1024];
__device__ float g_scratch[NROWS * PADW];
// Lerp lines per padded cell d: (A, B), value(yc) = A + B*yc, yc = yi - 256.
// A = v0 - (d - 384)*B   (384 = POFF + 256)
__device__ float2 g_lines[NROWS * PADW];

__global__ void init_g_kernel() {
    int k = blockIdx.x * blockDim.x + threadIdx.x;
    if (k >= 1024) return;
    int m = k - 512; if (m < 0) m = -m;
    float v = 0.0f;
    if (m == 0) v = 0.5f;
    else if (m & 1) {
        double pm = 3.141592653589793 * (double)m;
        v = (float)(-2.0 / (pm * pm));
    }
    g_filt2[k] = v;
}

__global__ void zero_scratch_kernel() {
    int i = blockIdx.x * blockDim.x + threadIdx.x;
    if (i < NROWS * PADW) g_scratch[i] = 0.0f;
}

// Ramp filter as symmetric Toeplitz matvec, parity split (even-|m| taps zero).
__global__ void __launch_bounds__(192) filt_kernel(const float* __restrict__ x) {
    __shared__ float gs[1024];
    for (int i = threadIdx.x; i < 1024; i += 192) gs[i] = g_filt2[i];
    __syncthreads();

    int b = blockIdx.y;
    int dbase = blockIdx.x * 8;        // always even
    int a = threadIdx.x;
    if (a >= NANG) return;

    const float* xb = x + (size_t)b * DET * NANG + a;

    float acc0 = 0.5f * xb[(dbase + 0) * NANG];
    float acc1 = 0.5f * xb[(dbase + 1) * NANG];
    float acc2 = 0.5f * xb[(dbase + 2) * NANG];
    float acc3 = 0.5f * xb[(dbase + 3) * NANG];
    float acc4 = 0.5f * xb[(dbase + 4) * NANG];
    float acc5 = 0.5f * xb[(dbase + 5) * NANG];
    float acc6 = 0.5f * xb[(dbase + 6) * NANG];
    float acc7 = 0.5f * xb[(dbase + 7) * NANG];

    const float* gp = gs + 512 + dbase;
    const float* xr = xb;

    #pragma unroll 4
    for (int j = 0; j < DET; j += 2) {
        float xe = xr[0];
        float xo = xr[NANG];
        xr += 2 * NANG;
        const float* g0 = gp - j;
        float gm1 = g0[-1], g1 = g0[1], g3 = g0[3], g5 = g0[5], g7 = g0[7];
        acc1 = fmaf(g1, xe, acc1);
        acc3 = fmaf(g3, xe, acc3);
        acc5 = fmaf(g5, xe, acc5);
        acc7 = fmaf(g7, xe, acc7);
        acc0 = fmaf(gm1, xo, acc0);
        acc2 = fmaf(g1,  xo, acc2);
        acc4 = fmaf(g3,  xo, acc4);
        acc6 = fmaf(g5,  xo, acc6);
    }

    float* out = g_scratch + ((size_t)b * NANG + a) * PADW + POFF + dbase;
    out[0] = acc0; out[1] = acc1; out[2] = acc2; out[3] = acc3;
    out[4] = acc4; out[5] = acc5; out[6] = acc6; out[7] = acc7;
}

// Build lerp lines. PADW=768 is NOT a power of two -> true modulo.
__global__ void __launch_bounds__(256) pack_kernel() {
    int idx = blockIdx.x * blockDim.x + threadIdx.x;
    if (idx >= NROWS * PADW) return;
    int row = idx / PADW;
    int d   = idx - row * PADW;
    float v0 = g_scratch[idx];
    float v1 = (d + 1 < PADW && idx + 1 < NROWS * PADW) ? g_scratch[idx + 1] : 0.0f;
    float B = v1 - v0;
    float A = fmaf(-((float)d - 384.0f), B, v0);   // 384 = POFF + 256
    g_lines[idx] = make_float2(A, B);
}

// Backprojection: 4 pixels/thread, 6-instr taps (floor index + line lerp).
__global__ void __launch_bounds__(256) bp_kernel(float* __restrict__ out) {
    __shared__ float2 cs[NANG];
    int tid = threadIdx.y * 32 + threadIdx.x;
    if (tid < NANG) {
        float th = (float)tid * 0.017453292519943295f;
        float s, c;
        sincosf(th, &s, &c);
        cs[tid] = make_float2(c * 255.5f, s * 255.5f);
    }
    __syncthreads();

    int b   = blockIdx.z;
    int ix  = blockIdx.x * 32 + threadIdx.x;
    int iy0 = blockIdx.y * 32 + threadIdx.y;   // pixels iy0, +8, +16, +24

    const float step = 2.0f / 511.0f;
    // no-FMA grid coords to track jnp.linspace rounding (mask sensitivity)
    float ux  = __fadd_rn(__fmul_rn((float)ix,        step), -1.0f);
    float uy0 = __fadd_rn(__fmul_rn((float)(iy0),      step), -1.0f);
    float uy1 = __fadd_rn(__fmul_rn((float)(iy0 + 8),  step), -1.0f);
    float uy2 = __fadd_rn(__fmul_rn((float)(iy0 + 16), step), -1.0f);
    float uy3 = __fadd_rn(__fmul_rn((float)(iy0 + 24), step), -1.0f);
    float nuy0 = -uy0, nuy1 = -uy1, nuy2 = -uy2, nuy3 = -uy3;

    // +384 (POFF + 256) folded into the row pointer; j is signed.
    const float2* p = g_lines + (size_t)b * NANG * PADW + 384;

    float acc0 = 0.0f, acc1 = 0.0f, acc2 = 0.0f, acc3 = 0.0f;
    #pragma unroll 4
    for (int a = 0; a < NANG; a++, p += PADW) {
        float2 t = cs[a];
        // yi = 255.5 + ux*t.x - uy*t.y ;  yc = yi - 256 = ux*t.x - uy*t.y - 0.5
        float xb = fmaf(ux, t.x, -0.5f);

        float yc0 = fmaf(nuy0, t.y, xb);
        float yc1 = fmaf(nuy1, t.y, xb);
        float yc2 = fmaf(nuy2, t.y, xb);
        float yc3 = fmaf(nuy3, t.y, xb);

        int j0 = __float2int_rd(yc0);
        int j1 = __float2int_rd(yc1);
        int j2 = __float2int_rd(yc2);
        int j3 = __float2int_rd(yc3);

        float2 q0 = p[j0];
        float2 q1 = p[j1];
        float2 q2 = p[j2];
        float2 q3 = p[j3];

        acc0 += fmaf(q0.y, yc0, q0.x);
        acc1 += fmaf(q1.y, yc1, q1.x);
        acc2 += fmaf(q2.y, yc2, q2.x);
        acc3 += fmaf(q3.y, yc3, q3.x);
    }

    const float scale = 0.008726646259971648f;  // pi/360
    float uxx = __fmul_rn(ux, ux);
    float r20 = __fadd_rn(uxx, __fmul_rn(uy0, uy0));
    float r21 = __fadd_rn(uxx, __fmul_rn(uy1, uy1));
    float r22 = __fadd_rn(uxx, __fmul_rn(uy2, uy2));
    float r23 = __fadd_rn(uxx, __fmul_rn(uy3, uy3));

    float* o = out + ((size_t)b * 512 + iy0) * 512 + ix;
    o[0]          = (r20 <= 1.0f) ? acc0 * scale : 0.0f;
    o[8 * 512]    = (r21 <= 1.0f) ? acc1 * scale : 0.0f;
    o[16 * 512]   = (r22 <= 1.0f) ? acc2 * scale : 0.0f;
    o[24 * 512]   = (r23 <= 1.0f) ? acc3 * scale : 0.0f;
}

extern "C" void kernel_launch(void* const* d_in, const int* in_sizes, int n_in,
                              void* d_out, int out_size) {
    const float* x = (const float*)d_in[0];
    float* out = (float*)d_out;

    init_g_kernel<<<2, 512>>>();
    zero_scratch_kernel<<<(NROWS * PADW + 255) / 256, 256>>>();
    filt_kernel<<<dim3(DET / 8, BATCH), 192>>>(x);
    pack_kernel<<<(NROWS * PADW + 255) / 256, 256>>>();
    bp_kernel<<<dim3(512 / 32, 512 / 32, BATCH), dim3(32, 8)>>>(out);
}